// round 1
// baseline (speedup 1.0000x reference)
#include <cuda_runtime.h>
#include <cstdint>
#include <cstddef>

#define HID 96
#define G3  288      // 3*H
#define TT  512
#define BB  512
#define II  100
#define BC  8        // batch elements per recurrence CTA

// Scratch for input projections: [dir][t*B + b][3H]  (604 MB, static __device__)
__device__ float g_xp[(size_t)2 * TT * BB * G3];

// ---------- packed fp32x2 helpers (Blackwell FFMA2 path) ----------
__device__ __forceinline__ unsigned long long pk2(float lo, float hi) {
    unsigned long long r;
    asm("mov.b64 %0, {%1, %2};" : "=l"(r) : "f"(lo), "f"(hi));
    return r;
}
__device__ __forceinline__ void upk2(unsigned long long v, float& lo, float& hi) {
    asm("mov.b64 {%0, %1}, %2;" : "=f"(lo), "=f"(hi) : "l"(v));
}
__device__ __forceinline__ unsigned long long fma2(unsigned long long a,
                                                   unsigned long long b,
                                                   unsigned long long c) {
    unsigned long long d;
    asm("fma.rn.f32x2 %0, %1, %2, %3;" : "=l"(d) : "l"(a), "l"(b), "l"(c));
    return d;
}

__device__ __forceinline__ float sigmoidf_(float x) {
    return __fdividef(1.f, 1.f + __expf(-x));
}
__device__ __forceinline__ float tanhf_(float x) {
    float e = __expf(-2.f * fabsf(x));
    float t = __fdividef(1.f - e, 1.f + e);
    return copysignf(t, x);
}

// =====================================================================
// Kernel A: input projection GEMM  xp[dir][row][g] = x[row] . w_ih[g] + b_ih[g]
//   M = T*B = 262144, N = 288, K = 100.  Tile BM=128 x BN=96, 256 threads,
//   micro-tile 8x6, fp32x2-packed accumulation along n.
// =====================================================================
#define A_BM 128
#define A_BN 96
#define A_LDS 101   // padded K stride (conflict-free transposeless layout)

__global__ void __launch_bounds__(256, 2) proj_kernel(
    const float* __restrict__ x,
    const float* __restrict__ w_ih_f, const float* __restrict__ b_ih_f,
    const float* __restrict__ w_ih_b, const float* __restrict__ b_ih_b)
{
    extern __shared__ float sm[];
    float* xs = sm;                    // [A_BM][A_LDS]
    float* ws = sm + A_BM * A_LDS;     // [A_BN][A_LDS]

    const int tid = threadIdx.x;
    const int dir = blockIdx.z;
    const float* w    = dir ? w_ih_b : w_ih_f;
    const float* bias = dir ? b_ih_b : b_ih_f;
    const size_t row0 = (size_t)blockIdx.x * A_BM;
    const int g0 = blockIdx.y * A_BN;

    // Load tiles (natural layout: coalesced global reads, conflict-free stores)
    for (int idx = tid; idx < A_BM * II; idx += 256) {
        int m = idx / II, i = idx - m * II;
        xs[m * A_LDS + i] = x[(row0 + m) * II + i];
    }
    for (int idx = tid; idx < A_BN * II; idx += 256) {
        int n = idx / II, i = idx - n * II;
        ws[n * A_LDS + i] = w[(size_t)(g0 + n) * II + i];
    }
    __syncthreads();

    const int ty = tid >> 4, tx = tid & 15;
    const int m0 = ty * 8, n0 = tx * 6;

    unsigned long long acc[8][3];
#pragma unroll
    for (int r = 0; r < 8; r++)
#pragma unroll
        for (int jp = 0; jp < 3; jp++) acc[r][jp] = 0ull;

#pragma unroll 2
    for (int i = 0; i < II; i++) {
        unsigned long long bp[3];
#pragma unroll
        for (int jp = 0; jp < 3; jp++)
            bp[jp] = pk2(ws[(n0 + 2 * jp) * A_LDS + i],
                         ws[(n0 + 2 * jp + 1) * A_LDS + i]);
#pragma unroll
        for (int r = 0; r < 8; r++) {
            float a = xs[(m0 + r) * A_LDS + i];
            unsigned long long ap = pk2(a, a);
#pragma unroll
            for (int jp = 0; jp < 3; jp++)
                acc[r][jp] = fma2(ap, bp[jp], acc[r][jp]);
        }
    }

    // Epilogue: add bias, write xp
#pragma unroll
    for (int r = 0; r < 8; r++) {
        size_t rowbase = ((size_t)dir * TT * BB + row0 + m0 + r) * G3;
#pragma unroll
        for (int jp = 0; jp < 3; jp++) {
            float lo, hi;
            upk2(acc[r][jp], lo, hi);
            int gg = g0 + n0 + 2 * jp;
            float2 v = make_float2(lo + bias[gg], hi + bias[gg + 1]);
            *(float2*)&g_xp[rowbase + gg] = v;
        }
    }
}

// =====================================================================
// Kernel B: GRU recurrence. One CTA = (dir, 8 batch elements), 576 threads.
//   Thread (g, half) holds 48 W_hh weights in registers (packed f32x2),
//   computes half-dot hp[b][g] for all 8 b per step. Gate phase combines.
//   No global sync — each CTA runs its full 512-step scan independently.
// =====================================================================
__global__ void __launch_bounds__(576, 1) gru_scan_kernel(
    const float* __restrict__ w_hh_f, const float* __restrict__ b_hh_f,
    const float* __restrict__ w_hh_b, const float* __restrict__ b_hh_b,
    float* __restrict__ out)
{
    __shared__ __align__(16) float hs [2][BC][HID];   // hidden state, double-buffered
    __shared__ __align__(16) float hps[2][BC][G3];    // half-dot partials [half][b][g]
    __shared__ __align__(16) float xps[2][BC][G3];    // staged x_proj, double-buffered
    __shared__ float bhs[G3];

    const int tid  = threadIdx.x;
    const int dir  = blockIdx.y;
    const int b0   = blockIdx.x * BC;
    const float* whh = dir ? w_hh_b : w_hh_f;
    const float* bhh = dir ? b_hh_b : b_hh_f;

    const int g    = tid % G3;   // 0..287
    const int half = tid / G3;   // 0 or 1

    // Preload this thread's 48 weights, packed as 24 f32x2 pairs
    unsigned long long w2[24];
    {
        const float4* wr = (const float4*)(whh + (size_t)g * HID + half * 48);
#pragma unroll
        for (int j = 0; j < 12; j++) {
            float4 f = wr[j];
            w2[2 * j]     = pk2(f.x, f.y);
            w2[2 * j + 1] = pk2(f.z, f.w);
        }
    }
    if (tid < G3) bhs[tid] = bhh[tid];
    for (int i = tid; i < BC * HID; i += 576) ((float*)hs[0])[i] = 0.f;
    {   // stage x_proj for step 0 (2304 floats = 576 float4, fully coalesced)
        int tt0 = dir ? (TT - 1) : 0;
        const float4* src = (const float4*)(g_xp +
            ((size_t)dir * TT * BB + (size_t)tt0 * BB + b0) * G3);
        ((float4*)xps[0])[tid] = src[tid];
    }
    __syncthreads();

    for (int s = 0; s < TT; s++) {
        const int cur = s & 1, nxt = cur ^ 1;
        const int tt = dir ? (TT - 1 - s) : s;

        // Prefetch next step's x_proj into registers (latency hidden by matvec)
        float4 xnext;
        {
            int s1  = (s + 1 < TT) ? s + 1 : s;
            int tt1 = dir ? (TT - 1 - s1) : s1;
            const float4* src = (const float4*)(g_xp +
                ((size_t)dir * TT * BB + (size_t)tt1 * BB + b0) * G3);
            xnext = src[tid];
        }

        // Phase 1: half matvec  hp_part[half][b][g] = W_hh[g, half*48 : +48] . h[b, ...]
#pragma unroll 2
        for (int b = 0; b < BC; b++) {
            const ulonglong2* h2 = (const ulonglong2*)(&hs[cur][b][half * 48]);
            unsigned long long a0 = 0ull, a1 = 0ull;
#pragma unroll
            for (int j = 0; j < 12; j++) {
                ulonglong2 h = h2[j];                   // 4 h-values, pre-packed pairs
                a0 = fma2(w2[2 * j],     h.x, a0);
                a1 = fma2(w2[2 * j + 1], h.y, a1);
            }
            float l0, h0v, l1, h1v;
            upk2(a0, l0, h0v);
            upk2(a1, l1, h1v);
            hps[half][b][g] = (l0 + h0v) + (l1 + h1v);
        }
        __syncthreads();

        // Phase 2: gates + state update + output write (768 units over 576 threads)
        {
            int u = tid;
#pragma unroll 1
            for (int rep = 0; rep < 2; rep++) {
                if (u < BC * HID) {
                    int b = u / HID, j = u - b * HID;
                    float hpr = hps[0][b][j]       + hps[1][b][j]       + bhs[j];
                    float hpz = hps[0][b][j + 96]  + hps[1][b][j + 96]  + bhs[j + 96];
                    float hpn = hps[0][b][j + 192] + hps[1][b][j + 192] + bhs[j + 192];
                    float r = sigmoidf_(xps[cur][b][j]       + hpr);
                    float z = sigmoidf_(xps[cur][b][j + 96]  + hpz);
                    float n = tanhf_  (xps[cur][b][j + 192] + r * hpn);
                    float hn = (1.f - z) * n + z * hs[cur][b][j];
                    hs[nxt][b][j] = hn;
                    out[((size_t)tt * BB + (b0 + b)) * (2 * HID) + dir * HID + j] = hn;
                }
                u += 576;
            }
            ((float4*)xps[nxt])[tid] = xnext;   // stage next step's x_proj
        }
        __syncthreads();
    }
}

// =====================================================================
extern "C" void kernel_launch(void* const* d_in, const int* in_sizes, int n_in,
                              void* d_out, int out_size)
{
    const float* x      = (const float*)d_in[0];
    const float* w_ih_f = (const float*)d_in[1];
    const float* w_hh_f = (const float*)d_in[2];
    const float* b_ih_f = (const float*)d_in[3];
    const float* b_hh_f = (const float*)d_in[4];
    const float* w_ih_b = (const float*)d_in[5];
    const float* w_hh_b = (const float*)d_in[6];
    const float* b_ih_b = (const float*)d_in[7];
    const float* b_hh_b = (const float*)d_in[8];
    float* out = (float*)d_out;

    size_t smA = (size_t)(A_BM * A_LDS + A_BN * A_LDS) * sizeof(float);  // ~90.5 KB
    cudaFuncSetAttribute(proj_kernel,
                         cudaFuncAttributeMaxDynamicSharedMemorySize, (int)smA);

    dim3 gA(TT * BB / A_BM, G3 / A_BN, 2);   // (2048, 3, 2)
    proj_kernel<<<gA, 256, smA>>>(x, w_ih_f, b_ih_f, w_ih_b, b_ih_b);

    dim3 gB(BB / BC, 2);                     // (64, 2) = 128 CTAs, one wave
    gru_scan_kernel<<<gB, 576>>>(w_hh_f, b_hh_f, w_hh_b, b_hh_b, out);
}

// round 3
// speedup vs baseline: 1.2321x; 1.2321x over previous
#include <cuda_runtime.h>
#include <cuda_bf16.h>
#include <cstdint>
#include <cstddef>

#define HID 96
#define G3  288      // 3*H
#define TT  512
#define BB  512
#define II  100
#define BC  8        // batch elements per recurrence CTA
#define KP  128      // padded K in g_wb storage
#define KPU 112      // padded K actually used by MMA (7 x k16)
#define PBM 128      // proj M tile
#define AST 120      // smem k-stride in halves (conflict-free: 60 words)

// Scratch for input projections: [dir][t*B + b][3H]
__device__ float g_xp[(size_t)2 * TT * BB * G3];
// Preconverted bf16-split weights: [dir][term(hi/lo)][288][128]
__device__ __nv_bfloat16 g_wb[(size_t)2 * 2 * G3 * KP];

// ---------- packed fp32x2 helpers (recurrence kernel) ----------
__device__ __forceinline__ unsigned long long pk2(float lo, float hi) {
    unsigned long long r;
    asm("mov.b64 %0, {%1, %2};" : "=l"(r) : "f"(lo), "f"(hi));
    return r;
}
__device__ __forceinline__ void upk2(unsigned long long v, float& lo, float& hi) {
    asm("mov.b64 {%0, %1}, %2;" : "=f"(lo), "=f"(hi) : "l"(v));
}
__device__ __forceinline__ unsigned long long fma2(unsigned long long a,
                                                   unsigned long long b,
                                                   unsigned long long c) {
    unsigned long long d;
    asm("fma.rn.f32x2 %0, %1, %2, %3;" : "=l"(d) : "l"(a), "l"(b), "l"(c));
    return d;
}
__device__ __forceinline__ float sigmoidf_(float x) {
    return __fdividef(1.f, 1.f + __expf(-x));
}
__device__ __forceinline__ float tanhf_(float x) {
    float e = __expf(-2.f * fabsf(x));
    float t = __fdividef(1.f - e, 1.f + e);
    return copysignf(t, x);
}

__device__ __forceinline__ void mma16816(float* c, const uint32_t* a, const uint32_t* b) {
    asm volatile(
        "mma.sync.aligned.m16n8k16.row.col.f32.bf16.bf16.f32 "
        "{%0,%1,%2,%3}, {%4,%5,%6,%7}, {%8,%9}, {%0,%1,%2,%3};"
        : "+f"(c[0]), "+f"(c[1]), "+f"(c[2]), "+f"(c[3])
        : "r"(a[0]), "r"(a[1]), "r"(a[2]), "r"(a[3]), "r"(b[0]), "r"(b[1]));
}

// =====================================================================
// Kernel 0: convert W_ih (both dirs) to bf16 hi/lo split, K zero-padded
// =====================================================================
__global__ void wconv_kernel(const float* __restrict__ wf, const float* __restrict__ wb)
{
    int idx = blockIdx.x * 256 + threadIdx.x;
    if (idx >= 2 * G3 * KP) return;
    int dir = idx / (G3 * KP);
    int rem = idx - dir * (G3 * KP);
    int n = rem / KP, k = rem - n * KP;
    const float* w = dir ? wb : wf;
    float v = (k < II) ? w[n * II + k] : 0.f;
    __nv_bfloat16 h = __float2bfloat16(v);
    __nv_bfloat16 l = __float2bfloat16(v - __bfloat162float(h));
    g_wb[((size_t)dir * 2 + 0) * G3 * KP + rem] = h;
    g_wb[((size_t)dir * 2 + 1) * G3 * KP + rem] = l;
}

// =====================================================================
// Kernel A: projection GEMM via mma.sync bf16 (3-term split, fp32 accum)
//   CTA: 128 rows x 96 gate-cols, K=112 (7 k16 steps). 8 warps (4m x 2n),
//   warp tile 32x48 = 2x6 m16n8k16 atoms. Manual LDS fragment loads from
//   padded row-major smem (stride 120 halves -> conflict-free).
// =====================================================================
#define SA0 0                      // A hi: 128*120*2 = 30720 B
#define SA1 30720                  // A lo
#define SB0 61440                  // B hi: 96*120*2 = 23040 B
#define SB1 84480                  // B lo
#define SBIAS 107520               // 96 floats
#define SMTOT (107520 + 96 * 4)

__global__ void __launch_bounds__(256) proj_mma_kernel(
    const float* __restrict__ x,
    const float* __restrict__ b_ih_f, const float* __restrict__ b_ih_b)
{
    extern __shared__ char smp[];
    const int tid = threadIdx.x, wid = tid >> 5, lid = tid & 31;
    const int dir = blockIdx.z;
    const int ny = blockIdx.y;                 // N-block (3 x 96)
    const size_t row0 = (size_t)blockIdx.x * PBM;
    const float* bias = dir ? b_ih_b : b_ih_f;
    float* bsm = (float*)(smp + SBIAS);

    // Zero A regions (pad coverage), load bias
    for (int i = tid; i < (2 * PBM * AST * 2) / 16; i += 256)
        ((uint4*)smp)[i] = make_uint4(0, 0, 0, 0);
    if (tid < 96) bsm[tid] = bias[ny * 96 + tid];
    __syncthreads();

    // Fill A: x rows -> bf16 hi/lo, row-major [128][120]
    {
        __nv_bfloat16* Ah = (__nv_bfloat16*)(smp + SA0);
        __nv_bfloat16* Al = (__nv_bfloat16*)(smp + SA1);
        for (int idx = tid; idx < PBM * II; idx += 256) {
            int r = idx / II, k = idx - r * II;
            float v = x[(row0 + r) * II + k];
            __nv_bfloat16 h = __float2bfloat16(v);
            __nv_bfloat16 l = __float2bfloat16(v - __bfloat162float(h));
            Ah[r * AST + k] = h;
            Al[r * AST + k] = l;
        }
    }
    // Fill B: preconverted weights, rows [96][120], k 0..111 (zeros beyond 100)
    for (int idx = tid; idx < 2 * 96 * (KPU / 8); idx += 256) {
        int term = idx / (96 * (KPU / 8));
        int rem = idx - term * (96 * (KPU / 8));
        int n = rem / (KPU / 8);
        int k8 = (rem - n * (KPU / 8)) * 8;
        uint4 v = *(const uint4*)&g_wb[(((size_t)dir * 2 + term) * G3 + ny * 96 + n) * KP + k8];
        *(uint4*)((__nv_bfloat16*)(smp + (term ? SB1 : SB0)) + n * AST + k8) = v;
    }
    __syncthreads();

    const int wm = wid & 3, wn = wid >> 2;
    const int m0 = wm * 32, n0 = wn * 48;
    const int gid = lid >> 2, tig = lid & 3;

    float acc[2][6][4];
#pragma unroll
    for (int i = 0; i < 2; i++)
#pragma unroll
        for (int j = 0; j < 6; j++)
#pragma unroll
            for (int q = 0; q < 4; q++) acc[i][j][q] = 0.f;

#pragma unroll 1
    for (int term = 0; term < 3; term++) {
        const __nv_bfloat16* As = (const __nv_bfloat16*)(smp + (term == 2 ? SA1 : SA0));
        const __nv_bfloat16* Bs = (const __nv_bfloat16*)(smp + (term == 1 ? SB1 : SB0));
#pragma unroll
        for (int ks = 0; ks < 7; ks++) {
            const int kk = ks * 16 + tig * 2;
            uint32_t a[2][4], b[6][2];
#pragma unroll
            for (int i = 0; i < 2; i++) {
                int r = m0 + i * 16 + gid;
                a[i][0] = *(const uint32_t*)&As[r * AST + kk];
                a[i][1] = *(const uint32_t*)&As[(r + 8) * AST + kk];
                a[i][2] = *(const uint32_t*)&As[r * AST + kk + 8];
                a[i][3] = *(const uint32_t*)&As[(r + 8) * AST + kk + 8];
            }
#pragma unroll
            for (int j = 0; j < 6; j++) {
                int n = n0 + j * 8 + gid;
                b[j][0] = *(const uint32_t*)&Bs[n * AST + kk];
                b[j][1] = *(const uint32_t*)&Bs[n * AST + kk + 8];
            }
#pragma unroll
            for (int i = 0; i < 2; i++)
#pragma unroll
                for (int j = 0; j < 6; j++)
                    mma16816(acc[i][j], a[i], b[j]);
        }
    }

    // Epilogue: add bias, write g_xp (float2 per row per atom)
#pragma unroll
    for (int i = 0; i < 2; i++) {
        size_t r = row0 + m0 + i * 16 + gid;
        size_t gb0 = ((size_t)dir * TT * BB + r) * G3;
        size_t gb1 = gb0 + 8 * G3;
#pragma unroll
        for (int j = 0; j < 6; j++) {
            int bn = n0 + j * 8 + tig * 2;
            float bz0 = bsm[bn], bz1 = bsm[bn + 1];
            int g = ny * 96 + bn;
            *(float2*)&g_xp[gb0 + g] = make_float2(acc[i][j][0] + bz0, acc[i][j][1] + bz1);
            *(float2*)&g_xp[gb1 + g] = make_float2(acc[i][j][2] + bz0, acc[i][j][3] + bz1);
        }
    }
}

// =====================================================================
// Kernel B: GRU recurrence (unchanged — known good)
// =====================================================================
__global__ void __launch_bounds__(576, 1) gru_scan_kernel(
    const float* __restrict__ w_hh_f, const float* __restrict__ b_hh_f,
    const float* __restrict__ w_hh_b, const float* __restrict__ b_hh_b,
    float* __restrict__ out)
{
    __shared__ __align__(16) float hs [2][BC][HID];
    __shared__ __align__(16) float hps[2][BC][G3];
    __shared__ __align__(16) float xps[2][BC][G3];
    __shared__ float bhs[G3];

    const int tid  = threadIdx.x;
    const int dir  = blockIdx.y;
    const int b0   = blockIdx.x * BC;
    const float* whh = dir ? w_hh_b : w_hh_f;
    const float* bhh = dir ? b_hh_b : b_hh_f;

    const int g    = tid % G3;
    const int half = tid / G3;

    unsigned long long w2[24];
    {
        const float4* wr = (const float4*)(whh + (size_t)g * HID + half * 48);
#pragma unroll
        for (int j = 0; j < 12; j++) {
            float4 f = wr[j];
            w2[2 * j]     = pk2(f.x, f.y);
            w2[2 * j + 1] = pk2(f.z, f.w);
        }
    }
    if (tid < G3) bhs[tid] = bhh[tid];
    for (int i = tid; i < BC * HID; i += 576) ((float*)hs[0])[i] = 0.f;
    {
        int tt0 = dir ? (TT - 1) : 0;
        const float4* src = (const float4*)(g_xp +
            ((size_t)dir * TT * BB + (size_t)tt0 * BB + b0) * G3);
        ((float4*)xps[0])[tid] = src[tid];
    }
    __syncthreads();

    for (int s = 0; s < TT; s++) {
        const int cur = s & 1, nxt = cur ^ 1;
        const int tt = dir ? (TT - 1 - s) : s;

        float4 xnext;
        {
            int s1  = (s + 1 < TT) ? s + 1 : s;
            int tt1 = dir ? (TT - 1 - s1) : s1;
            const float4* src = (const float4*)(g_xp +
                ((size_t)dir * TT * BB + (size_t)tt1 * BB + b0) * G3);
            xnext = src[tid];
        }

#pragma unroll 2
        for (int b = 0; b < BC; b++) {
            const ulonglong2* h2 = (const ulonglong2*)(&hs[cur][b][half * 48]);
            unsigned long long a0 = 0ull, a1 = 0ull;
#pragma unroll
            for (int j = 0; j < 12; j++) {
                ulonglong2 h = h2[j];
                a0 = fma2(w2[2 * j],     h.x, a0);
                a1 = fma2(w2[2 * j + 1], h.y, a1);
            }
            float l0, h0v, l1, h1v;
            upk2(a0, l0, h0v);
            upk2(a1, l1, h1v);
            hps[half][b][g] = (l0 + h0v) + (l1 + h1v);
        }
        __syncthreads();

        {
            int u = tid;
#pragma unroll 1
            for (int rep = 0; rep < 2; rep++) {
                if (u < BC * HID) {
                    int b = u / HID, j = u - b * HID;
                    float hpr = hps[0][b][j]       + hps[1][b][j]       + bhs[j];
                    float hpz = hps[0][b][j + 96]  + hps[1][b][j + 96]  + bhs[j + 96];
                    float hpn = hps[0][b][j + 192] + hps[1][b][j + 192] + bhs[j + 192];
                    float r = sigmoidf_(xps[cur][b][j]       + hpr);
                    float z = sigmoidf_(xps[cur][b][j + 96]  + hpz);
                    float n = tanhf_  (xps[cur][b][j + 192] + r * hpn);
                    float hn = (1.f - z) * n + z * hs[cur][b][j];
                    hs[nxt][b][j] = hn;
                    out[((size_t)tt * BB + (b0 + b)) * (2 * HID) + dir * HID + j] = hn;
                }
                u += 576;
            }
            ((float4*)xps[nxt])[tid] = xnext;
        }
        __syncthreads();
    }
}

// =====================================================================
extern "C" void kernel_launch(void* const* d_in, const int* in_sizes, int n_in,
                              void* d_out, int out_size)
{
    const float* x      = (const float*)d_in[0];
    const float* w_ih_f = (const float*)d_in[1];
    const float* w_hh_f = (const float*)d_in[2];
    const float* b_ih_f = (const float*)d_in[3];
    const float* b_hh_f = (const float*)d_in[4];
    const float* w_ih_b = (const float*)d_in[5];
    const float* w_hh_b = (const float*)d_in[6];
    const float* b_ih_b = (const float*)d_in[7];
    const float* b_hh_b = (const float*)d_in[8];
    float* out = (float*)d_out;

    wconv_kernel<<<(2 * G3 * KP + 255) / 256, 256>>>(w_ih_f, w_ih_b);

    cudaFuncSetAttribute(proj_mma_kernel,
                         cudaFuncAttributeMaxDynamicSharedMemorySize, SMTOT);
    dim3 gA(TT * BB / PBM, 3, 2);            // (2048, 3, 2)
    proj_mma_kernel<<<gA, 256, SMTOT>>>(x, b_ih_f, b_ih_b);

    dim3 gB(BB / BC, 2);                     // 128 CTAs, one wave
    gru_scan_kernel<<<gB, 576>>>(w_hh_f, b_hh_f, w_hh_b, b_hh_b, out);
}

// round 7
// speedup vs baseline: 1.2738x; 1.0339x over previous
#include <cuda_runtime.h>
#include <cuda_bf16.h>
#include <cstdint>
#include <cstddef>

#define HID 96
#define G3  288      // 3*H
#define TT  512
#define BB  512
#define II  100
#define BC  8        // batch elements per recurrence CTA
#define MM  (TT * BB)
#define KPU 112      // padded K used by MMA (7 x k16)
#define PBM 128      // proj M tile
#define AST 120      // smem k-stride in halves (conflict-free)

// Scratch: input projections [dir][t*B + b][3H]
__device__ float g_xp[(size_t)2 * MM * G3];
// Pre-split bf16 weights: [dir][term][288][112]
__device__ __nv_bfloat16 g_wb[(size_t)2 * 2 * G3 * KPU];
// Pre-split bf16 inputs: [term][M][112]
__device__ __nv_bfloat16 g_xb[(size_t)2 * MM * KPU];

// ---------- packed fp32x2 helpers ----------
__device__ __forceinline__ unsigned long long pk2(float lo, float hi) {
    unsigned long long r;
    asm("mov.b64 %0, {%1, %2};" : "=l"(r) : "f"(lo), "f"(hi));
    return r;
}
__device__ __forceinline__ void upk2(unsigned long long v, float& lo, float& hi) {
    asm("mov.b64 {%0, %1}, %2;" : "=f"(lo), "=f"(hi) : "l"(v));
}
__device__ __forceinline__ unsigned long long fma2(unsigned long long a,
                                                   unsigned long long b,
                                                   unsigned long long c) {
    unsigned long long d;
    asm("fma.rn.f32x2 %0, %1, %2, %3;" : "=l"(d) : "l"(a), "l"(b), "l"(c));
    return d;
}
__device__ __forceinline__ float sigmoidf_(float x) {
    return __fdividef(1.f, 1.f + __expf(-x));
}
__device__ __forceinline__ float tanhf_(float x) {
    float e = __expf(-2.f * fabsf(x));
    float t = __fdividef(1.f - e, 1.f + e);
    return copysignf(t, x);
}
__device__ __forceinline__ void mma16816(float* c, const uint32_t* a, const uint32_t* b) {
    asm volatile(
        "mma.sync.aligned.m16n8k16.row.col.f32.bf16.bf16.f32 "
        "{%0,%1,%2,%3}, {%4,%5,%6,%7}, {%8,%9}, {%0,%1,%2,%3};"
        : "+f"(c[0]), "+f"(c[1]), "+f"(c[2]), "+f"(c[3])
        : "r"(a[0]), "r"(a[1]), "r"(a[2]), "r"(a[3]), "r"(b[0]), "r"(b[1]));
}

// =====================================================================
// Kernel W: W_ih -> bf16 hi/lo, K padded to 112
// =====================================================================
__global__ void wconv_kernel(const float* __restrict__ wf, const float* __restrict__ wb)
{
    int idx = blockIdx.x * 256 + threadIdx.x;
    if (idx >= 2 * G3 * KPU) return;
    int dir = idx / (G3 * KPU);
    int rem = idx - dir * (G3 * KPU);
    int n = rem / KPU, k = rem - n * KPU;
    const float* w = dir ? wb : wf;
    float v = (k < II) ? w[n * II + k] : 0.f;
    __nv_bfloat16 h = __float2bfloat16(v);
    __nv_bfloat16 l = __float2bfloat16(v - __bfloat162float(h));
    g_wb[((size_t)dir * 2 + 0) * G3 * KPU + rem] = h;
    g_wb[((size_t)dir * 2 + 1) * G3 * KPU + rem] = l;
}

// =====================================================================
// Kernel X: x -> bf16 hi/lo, [term][M][112]
// =====================================================================
__global__ void xconv_kernel(const float* __restrict__ x)
{
    int idx = blockIdx.x * 256 + threadIdx.x;
    if (idx >= MM * KPU) return;
    int r = idx / KPU, k = idx - r * KPU;
    float v = (k < II) ? x[(size_t)r * II + k] : 0.f;
    __nv_bfloat16 h = __float2bfloat16(v);
    __nv_bfloat16 l = __float2bfloat16(v - __bfloat162float(h));
    g_xb[idx] = h;
    g_xb[(size_t)MM * KPU + idx] = l;
}

// =====================================================================
// Kernel A: projection GEMM via mma.sync bf16 (3-term split, fp32 accum)
//   CTA: 128 rows x 96 gate-cols, K=112. 8 warps (4m x 2n), warp 32x48.
//   Fills are pure uint4 copies from pre-split bf16 tensors.
// =====================================================================
#define SA0 0                      // A hi: 128*120*2 = 30720 B
#define SA1 30720                  // A lo
#define SB0 61440                  // B hi: 96*120*2 = 23040 B
#define SB1 84480                  // B lo
#define SBIAS 107520               // 96 floats
#define SMTOT (107520 + 96 * 4)

__global__ void __launch_bounds__(256) proj_mma_kernel(
    const float* __restrict__ b_ih_f, const float* __restrict__ b_ih_b)
{
    extern __shared__ char smp[];
    const int tid = threadIdx.x, wid = tid >> 5, lid = tid & 31;
    const int dir = blockIdx.z;
    const int ny = blockIdx.y;                 // N-block (3 x 96)
    const size_t row0 = (size_t)blockIdx.x * PBM;
    const float* bias = dir ? b_ih_b : b_ih_f;
    float* bsm = (float*)(smp + SBIAS);

    if (tid < 96) bsm[tid] = bias[ny * 96 + tid];

    // Fill A: 2 terms x 128 rows x 14 uint4 = 3584 copies
    for (int idx = tid; idx < 3584; idx += 256) {
        int term = idx / 1792;
        int rem = idx - term * 1792;
        int r = rem / 14, k8 = (rem - r * 14) * 8;
        uint4 v = *(const uint4*)&g_xb[((size_t)term * MM + row0 + r) * KPU + k8];
        *(uint4*)((__nv_bfloat16*)(smp + (term ? SA1 : SA0)) + r * AST + k8) = v;
    }
    // Fill B: 2 terms x 96 rows x 14 uint4 = 2688 copies
    for (int idx = tid; idx < 2688; idx += 256) {
        int term = idx / 1344;
        int rem = idx - term * 1344;
        int n = rem / 14, k8 = (rem - n * 14) * 8;
        uint4 v = *(const uint4*)&g_wb[(((size_t)dir * 2 + term) * G3 + ny * 96 + n) * KPU + k8];
        *(uint4*)((__nv_bfloat16*)(smp + (term ? SB1 : SB0)) + n * AST + k8) = v;
    }
    __syncthreads();

    const int wm = wid & 3, wn = wid >> 2;
    const int m0 = wm * 32, n0 = wn * 48;
    const int gid = lid >> 2, tig = lid & 3;

    float acc[2][6][4];
#pragma unroll
    for (int i = 0; i < 2; i++)
#pragma unroll
        for (int j = 0; j < 6; j++)
#pragma unroll
            for (int q = 0; q < 4; q++) acc[i][j][q] = 0.f;

#pragma unroll 1
    for (int term = 0; term < 3; term++) {
        const __nv_bfloat16* As = (const __nv_bfloat16*)(smp + (term == 2 ? SA1 : SA0));
        const __nv_bfloat16* Bs = (const __nv_bfloat16*)(smp + (term == 1 ? SB1 : SB0));
#pragma unroll
        for (int ks = 0; ks < 7; ks++) {
            const int kk = ks * 16 + tig * 2;
            uint32_t a[2][4], b[6][2];
#pragma unroll
            for (int i = 0; i < 2; i++) {
                int r = m0 + i * 16 + gid;
                a[i][0] = *(const uint32_t*)&As[r * AST + kk];
                a[i][1] = *(const uint32_t*)&As[(r + 8) * AST + kk];
                a[i][2] = *(const uint32_t*)&As[r * AST + kk + 8];
                a[i][3] = *(const uint32_t*)&As[(r + 8) * AST + kk + 8];
            }
#pragma unroll
            for (int j = 0; j < 6; j++) {
                int n = n0 + j * 8 + gid;
                b[j][0] = *(const uint32_t*)&Bs[n * AST + kk];
                b[j][1] = *(const uint32_t*)&Bs[n * AST + kk + 8];
            }
#pragma unroll
            for (int i = 0; i < 2; i++)
#pragma unroll
                for (int j = 0; j < 6; j++)
                    mma16816(acc[i][j], a[i], b[j]);
        }
    }

    // Epilogue: add bias, write g_xp
#pragma unroll
    for (int i = 0; i < 2; i++) {
        size_t r = row0 + m0 + i * 16 + gid;
        size_t gb0 = ((size_t)dir * MM + r) * G3;
        size_t gb1 = gb0 + 8 * G3;
#pragma unroll
        for (int j = 0; j < 6; j++) {
            int bn = n0 + j * 8 + tig * 2;
            float bz0 = bsm[bn], bz1 = bsm[bn + 1];
            int g = ny * 96 + bn;
            *(float2*)&g_xp[gb0 + g] = make_float2(acc[i][j][0] + bz0, acc[i][j][1] + bz1);
            *(float2*)&g_xp[gb1 + g] = make_float2(acc[i][j][2] + bz0, acc[i][j][3] + bz1);
        }
    }
}

// =====================================================================
// Kernel B: GRU recurrence. CTA = (dir, 8 batch), 864 threads.
//   Thread (g, third) holds 32 W_hh weights in regs; third-dots of 32.
//   27 warps/SM for latency hiding; 4 accumulation chains.
// =====================================================================
__global__ void __launch_bounds__(864, 1) gru_scan_kernel(
    const float* __restrict__ w_hh_f, const float* __restrict__ b_hh_f,
    const float* __restrict__ w_hh_b, const float* __restrict__ b_hh_b,
    float* __restrict__ out)
{
    __shared__ __align__(16) float hs [2][BC][HID];
    __shared__ __align__(16) float hps[3][BC][G3];   // [third][b][g]
    __shared__ __align__(16) float xps[2][BC][G3];
    __shared__ float bhs[G3];

    const int tid  = threadIdx.x;
    const int dir  = blockIdx.y;
    const int b0   = blockIdx.x * BC;
    const float* whh = dir ? w_hh_b : w_hh_f;
    const float* bhh = dir ? b_hh_b : b_hh_f;

    const int g     = tid % G3;   // 0..287
    const int third = tid / G3;   // 0..2

    // 32 weights -> 16 packed f32x2 pairs
    unsigned long long w2[16];
    {
        const float4* wr = (const float4*)(whh + (size_t)g * HID + third * 32);
#pragma unroll
        for (int j = 0; j < 8; j++) {
            float4 f = wr[j];
            w2[2 * j]     = pk2(f.x, f.y);
            w2[2 * j + 1] = pk2(f.z, f.w);
        }
    }
    if (tid < G3) bhs[tid] = bhh[tid];
    for (int i = tid; i < BC * HID; i += 864) ((float*)hs[0])[i] = 0.f;
    if (tid < 576) {
        int tt0 = dir ? (TT - 1) : 0;
        const float4* src = (const float4*)(g_xp +
            ((size_t)dir * MM + (size_t)tt0 * BB + b0) * G3);
        ((float4*)xps[0])[tid] = src[tid];
    }
    __syncthreads();

    for (int s = 0; s < TT; s++) {
        const int cur = s & 1, nxt = cur ^ 1;
        const int tt = dir ? (TT - 1 - s) : s;

        float4 xnext = make_float4(0.f, 0.f, 0.f, 0.f);
        if (tid < 576) {
            int s1  = (s + 1 < TT) ? s + 1 : s;
            int tt1 = dir ? (TT - 1 - s1) : s1;
            const float4* src = (const float4*)(g_xp +
                ((size_t)dir * MM + (size_t)tt1 * BB + b0) * G3);
            xnext = src[tid];
        }

        // Phase 1: third-dot  hps[third][b][g] = W_hh[g, third*32 : +32] . h[b, ...]
#pragma unroll 2
        for (int b = 0; b < BC; b++) {
            const ulonglong2* h2 = (const ulonglong2*)(&hs[cur][b][third * 32]);
            unsigned long long a0 = 0ull, a1 = 0ull, a2 = 0ull, a3 = 0ull;
#pragma unroll
            for (int j = 0; j < 8; j += 2) {
                ulonglong2 ha = h2[j];
                ulonglong2 hb = h2[j + 1];
                a0 = fma2(w2[2 * j],     ha.x, a0);
                a1 = fma2(w2[2 * j + 1], ha.y, a1);
                a2 = fma2(w2[2 * j + 2], hb.x, a2);
                a3 = fma2(w2[2 * j + 3], hb.y, a3);
            }
            float p0, p1, p2, p3, p4, p5, p6, p7;
            upk2(a0, p0, p1); upk2(a1, p2, p3);
            upk2(a2, p4, p5); upk2(a3, p6, p7);
            hps[third][b][g] = ((p0 + p1) + (p2 + p3)) + ((p4 + p5) + (p6 + p7));
        }
        __syncthreads();

        // Phase 2: gates + state update (768 units, single pass)
        if (tid < BC * HID) {
            int b = tid / HID, j = tid - b * HID;
            float hpr = hps[0][b][j]       + hps[1][b][j]       + hps[2][b][j]       + bhs[j];
            float hpz = hps[0][b][j + 96]  + hps[1][b][j + 96]  + hps[2][b][j + 96]  + bhs[j + 96];
            float hpn = hps[0][b][j + 192] + hps[1][b][j + 192] + hps[2][b][j + 192] + bhs[j + 192];
            float r = sigmoidf_(xps[cur][b][j]       + hpr);
            float z = sigmoidf_(xps[cur][b][j + 96]  + hpz);
            float n = tanhf_  (xps[cur][b][j + 192] + r * hpn);
            float hn = (1.f - z) * n + z * hs[cur][b][j];
            hs[nxt][b][j] = hn;
            out[((size_t)tt * BB + (b0 + b)) * (2 * HID) + dir * HID + j] = hn;
        }
        if (tid < 576) ((float4*)xps[nxt])[tid] = xnext;
        __syncthreads();
    }
}

// =====================================================================
extern "C" void kernel_launch(void* const* d_in, const int* in_sizes, int n_in,
                              void* d_out, int out_size)
{
    const float* x      = (const float*)d_in[0];
    const float* w_ih_f = (const float*)d_in[1];
    const float* w_hh_f = (const float*)d_in[2];
    const float* b_ih_f = (const float*)d_in[3];
    const float* b_hh_f = (const float*)d_in[4];
    const float* w_ih_b = (const float*)d_in[5];
    const float* w_hh_b = (const float*)d_in[6];
    const float* b_ih_b = (const float*)d_in[7];
    const float* b_hh_b = (const float*)d_in[8];
    float* out = (float*)d_out;

    wconv_kernel<<<(2 * G3 * KPU + 255) / 256, 256>>>(w_ih_f, w_ih_b);
    xconv_kernel<<<(MM * KPU + 255) / 256, 256>>>(x);

    cudaFuncSetAttribute(proj_mma_kernel,
                         cudaFuncAttributeMaxDynamicSharedMemorySize, SMTOT);
    dim3 gA(MM / PBM, 3, 2);                 // (2048, 3, 2)
    proj_mma_kernel<<<gA, 256, SMTOT>>>(b_ih_f, b_ih_b);

    dim3 gB(BB / BC, 2);                     // 128 CTAs, one wave
    gru_scan_kernel<<<gB, 864>>>(w_hh_f, b_hh_f, w_hh_b, b_hh_b, out);
}